// round 10
// baseline (speedup 1.0000x reference)
#include <cuda_runtime.h>
#include <cuda_fp16.h>
#include <cstdint>

// ---------------- problem constants ----------------
constexpr int B_  = 4;
constexpr int C_  = 64;
constexpr int HH  = 96;
constexpr int WW  = 96;
constexpr int N_  = HH * WW;        // 9216
constexpr int M_  = N_ / 2;         // 4608
constexpr int CI  = 32;
constexpr int TKV = 128;            // kv tile
constexpr int NT  = M_ / TKV;       // 36

// ---------------- scratch ----------------
// theta/phi rows: [b][n][64] fp16: halfwords 0-31 = hi (word-permuted), 32-63 = lo
// theta pre-scaled by log2(e): softmax in exp2 domain.
__device__ __half g_theta[(size_t)B_ * N_ * 64];
__device__ __half g_phi  [(size_t)B_ * M_ * 64];
// V: [b][ci][m] fp16, m permuted within 64-element runs
__device__ __half g_v[(size_t)B_ * CI * M_];

// ---------------- smem map (bytes, dynamic) ----------------
constexpr int KBUF = 24576;        // 128 x 192B
constexpr int VBUF = 10240;        // 32 x 320B
constexpr int SM_Q   = 0;          // 12288
constexpr int SM_K   = 12288;      // 2 x KBUF = 49152
constexpr int SM_V   = 61440;      // 3 x VBUF = 30720
constexpr int SM_LS  = 92160;      // 64 f32
constexpr int SM_MS  = 92416;      // 64 f32
constexpr int SMEM_TOTAL = 92672;  // x2 CTAs = 185KB <= 228KB
constexpr int KROW = 192;   // stride/16 = 12 == 4 mod 8 -> conflict-free LDS.128
constexpr int VROW = 320;   // stride/16 = 20 == 4 mod 8

// word permutation: within a 16-word group, logical word w -> phys 4*(w%4)+(w/4)
__host__ __device__ __forceinline__ int permw16(int w) {
    return (w & ~15) | ((w & 3) << 2) | ((w & 15) >> 2);
}

// ---------------- helpers ----------------
__device__ __forceinline__ uint32_t smem_u32(const void* p) {
    uint32_t a;
    asm("{ .reg .u64 t; cvta.to.shared.u64 t, %1; cvt.u32.u64 %0, t; }" : "=r"(a) : "l"(p));
    return a;
}

#define MMA4(cv, a0, a1, a2, a3, b0v, b1v)                                        \
    asm volatile("mma.sync.aligned.m16n8k16.row.col.f32.f16.f16.f32 "             \
        "{%0,%1,%2,%3}, {%4,%5,%6,%7}, {%8,%9}, {%0,%1,%2,%3};"                   \
        : "+f"((cv)[0]), "+f"((cv)[1]), "+f"((cv)[2]), "+f"((cv)[3])              \
        : "r"(a0), "r"(a1), "r"(a2), "r"(a3), "r"(b0v), "r"(b1v))

// D = A*B + 0 (separate zero C operand: avoids 4 MOV-inits per accumulator)
#define MMA4Z(cv, a0, a1, a2, a3, b0v, b1v, zz)                                   \
    asm volatile("mma.sync.aligned.m16n8k16.row.col.f32.f16.f16.f32 "             \
        "{%0,%1,%2,%3}, {%4,%5,%6,%7}, {%8,%9}, {%10,%10,%10,%10};"               \
        : "=f"((cv)[0]), "=f"((cv)[1]), "=f"((cv)[2]), "=f"((cv)[3])              \
        : "r"(a0), "r"(a1), "r"(a2), "r"(a3), "r"(b0v), "r"(b1v), "f"(zz))

#define CP16(dst, src)                                                            \
    asm volatile("cp.async.cg.shared.global [%0], [%1], 16;" :: "r"(dst), "l"(src) : "memory")

// exp2, deg-4 Taylor, FMA pipe only. Rescale args are exact integer diffs.
__device__ __forceinline__ float fexp2(float d) {
    float t = d + 12582912.0f;
    float f = d - (t - 12582912.0f);
    float p = 0.00961813f;
    p = fmaf(p, f, 0.05550411f);
    p = fmaf(p, f, 0.24022651f);
    p = fmaf(p, f, 0.69314718f);
    p = fmaf(p, f, 1.0f);
    return __int_as_float(__float_as_int(t) * 8388608 + __float_as_int(p));
}

// exp2(c - m) with INTEGER m folded into K1 = 12582912 - m (exact).
__device__ __forceinline__ float fexp2f(float c, float K1) {
    float t = c + K1;
    float u = K1 - t;
    float f = u + c;
    float p = 0.00961813f;
    p = fmaf(p, f, 0.05550411f);
    p = fmaf(p, f, 0.24022651f);
    p = fmaf(p, f, 0.69314718f);
    p = fmaf(p, f, 1.0f);
    return __int_as_float(__float_as_int(t) * 8388608 + __float_as_int(p));
}

__device__ __forceinline__ uint32_t pkh2(float a, float b) {
    __half2 h = __floats2half2_rn(a, b);
    uint32_t u; *reinterpret_cast<__half2*>(&u) = h;
    return u;
}

// =====================================================================
// Kernel A: projections -> fp16 hi/lo scratch (permuted layouts)
// grid (144, 4), 256 threads
// =====================================================================
__global__ __launch_bounds__(256)
void proj_kernel(const float* __restrict__ x,
                 const float* __restrict__ wt, const float* __restrict__ bt,
                 const float* __restrict__ wp, const float* __restrict__ bp,
                 const float* __restrict__ wg, const float* __restrict__ bg)
{
    __shared__ float xs[C_][64];
    __shared__ float ws[3][CI][C_];
    __shared__ float bs[3][CI];

    const int b   = blockIdx.y;
    const int n0  = blockIdx.x * 64;
    const int m0  = blockIdx.x * 32;
    const int tid = threadIdx.x;

    float* wflat = &ws[0][0][0];
    for (int i = tid; i < CI * C_; i += 256) {
        wflat[i]               = wt[i];
        wflat[CI * C_ + i]     = wp[i];
        wflat[2 * CI * C_ + i] = wg[i];
    }
    if (tid < CI) { bs[0][tid] = bt[tid]; bs[1][tid] = bp[tid]; bs[2][tid] = bg[tid]; }
    for (int idx = tid; idx < C_ * 64; idx += 256) {
        const int c = idx >> 6, j = idx & 63;
        xs[c][j] = x[((size_t)b * C_ + c) * N_ + n0 + j];
    }
    __syncthreads();

    const int j   = tid & 63;
    const int cib = tid >> 6;
    float tacc[8];
#pragma unroll
    for (int u = 0; u < 8; u++) tacc[u] = bs[0][cib + 4 * u];
#pragma unroll 4
    for (int c = 0; c < C_; c++) {
        const float xv = xs[c][j];
#pragma unroll
        for (int u = 0; u < 8; u++) tacc[u] += xv * ws[0][cib + 4 * u][c];
    }

    const int jp  = tid & 31;
    const int cjb = tid >> 5;
    float pv[4], gv[4];
    {
        float p0[4], p1[4], q0[4], q1[4];
#pragma unroll
        for (int u = 0; u < 4; u++) { p0[u] = p1[u] = q0[u] = q1[u] = 0.f; }
#pragma unroll 4
        for (int c = 0; c < C_; c++) {
            const float x0 = xs[c][2 * jp];
            const float x1 = xs[c][2 * jp + 1];
#pragma unroll
            for (int u = 0; u < 4; u++) {
                const float wpv = ws[1][cjb + 8 * u][c];
                const float wgv = ws[2][cjb + 8 * u][c];
                p0[u] += x0 * wpv;  p1[u] += x1 * wpv;
                q0[u] += x0 * wgv;  q1[u] += x1 * wgv;
            }
        }
#pragma unroll
        for (int u = 0; u < 4; u++) {
            const int ci = cjb + 8 * u;
            pv[u] = bs[1][ci] + fmaxf(p0[u], p1[u]);
            gv[u] = bs[2][ci] + fmaxf(q0[u], q1[u]);
        }
    }
    __syncthreads();

    __half* sth = reinterpret_cast<__half*>(wflat);
    __half* sph = reinterpret_cast<__half*>(wflat + CI * C_);
#pragma unroll
    for (int u = 0; u < 8; u++) {
        const int ci  = cib + 4 * u;
        const int pos = permw16(ci >> 1) * 2 + (ci & 1);
        const float v = tacc[u] * 1.4426950408889634f;
        const __half h = __float2half_rn(v);
        sth[j * 64 + pos]      = h;
        sth[j * 64 + 32 + pos] = __float2half_rn(v - __half2float(h));
    }
#pragma unroll
    for (int u = 0; u < 4; u++) {
        const int ci  = cjb + 8 * u;
        const int pos = permw16(ci >> 1) * 2 + (ci & 1);
        {
            const float v = pv[u];
            const __half h = __float2half_rn(v);
            sph[jp * 64 + pos]      = h;
            sph[jp * 64 + 32 + pos] = __float2half_rn(v - __half2float(h));
        }
        {
            const int m    = m0 + jp;
            const int mloc = m & 63;
            const int mp   = (m & ~63) | (permw16(mloc >> 1) * 2 + (mloc & 1));
            g_v[((size_t)b * CI + ci) * M_ + mp] = __float2half_rn(gv[u]);
        }
    }
    __syncthreads();

    for (int idx = tid; idx < 512; idx += 256) {
        const int r = idx >> 3, c = idx & 7;
        *reinterpret_cast<uint4*>(&g_theta[((size_t)b * N_ + n0 + r) * 64 + c * 8]) =
            *reinterpret_cast<const uint4*>(&sth[r * 64 + c * 8]);
    }
    for (int idx = tid; idx < 256; idx += 256) {
        const int r = idx >> 3, c = idx & 7;
        *reinterpret_cast<uint4*>(&g_phi[((size_t)b * M_ + m0 + r) * 64 + c * 8]) =
            *reinterpret_cast<const uint4*>(&sph[r * 64 + c * 8]);
    }
}

// =====================================================================
// Kernel B: mma.sync fp16 flash attention, cross-tile pipelined:
//   iteration u: S(u+1) HMMA + O(u) HMMA (independent) + epi(u+1)
// grid (144, 4), 256 threads (8 warps), 2 CTAs/SM
// =====================================================================
__global__ __launch_bounds__(256, 2)
void attn_kernel(const float* __restrict__ x,
                 const float* __restrict__ w_out,
                 const float* __restrict__ b_out,
                 float* __restrict__ out)
{
    extern __shared__ char smem[];
    const uint32_t sbase = smem_u32(smem);
    const int tid  = threadIdx.x;
    const int wid  = tid >> 5;
    const int lane = tid & 31;
    const int wq   = wid & 3;
    const int ch   = wid >> 2;
    const int g    = lane >> 2;
    const int tig  = lane & 3;
    const int b    = blockIdx.y;
    const int n0   = blockIdx.x * 64;

    const __half* Qg = g_theta + ((size_t)b * N_ + n0) * 64;
    const __half* Kg = g_phi   + (size_t)b * M_ * 64;
    const __half* Vg = g_v     + (size_t)b * CI * M_;

    // ---- stage Q ----
    for (int i = tid; i < 512; i += 256) {
        const int r = i >> 3, c = i & 7;
        *reinterpret_cast<uint4*>(smem + SM_Q + r * KROW + c * 16) =
            *reinterpret_cast<const uint4*>(Qg + (size_t)r * 64 + c * 8);
    }

    const int kc = tid & 7;
    const int vc = tid & 15;
    // K -> buf t%2, V -> buf t%3
    auto issue_tile = [&](int t) {
        const __half* kb = Kg + (size_t)t * TKV * 64;
        const __half* vb = Vg + (size_t)t * TKV;
        const uint32_t kd = sbase + SM_K + (t & 1) * KBUF;
        const uint32_t vd = sbase + SM_V + (t % 3) * VBUF;
#pragma unroll
        for (int i = 0; i < 4; i++) {
            const int r = (tid + i * 256) >> 3;
            CP16(kd + r * KROW + kc * 16, kb + (size_t)r * 64 + kc * 8);
        }
#pragma unroll
        for (int i = 0; i < 2; i++) {
            const int ci = (tid + i * 256) >> 4;
            CP16(vd + ci * VROW + vc * 16, vb + (size_t)ci * M_ + vc * 8);
        }
    };

    issue_tile(0);
    asm volatile("cp.async.commit_group;" ::: "memory");
    issue_tile(1);
    asm volatile("cp.async.commit_group;" ::: "memory");
    __syncthreads();   // Q visible

    // ---- Q fragments ----
    uint32_t qh[2][4], ql[2][4];
    {
        const char* q1 = smem + SM_Q + (16 * wq + g) * KROW + 16 * tig;
        const char* q2 = smem + SM_Q + (16 * wq + g + 8) * KROW + 16 * tig;
        const uint4 hA = *reinterpret_cast<const uint4*>(q1);
        const uint4 hB = *reinterpret_cast<const uint4*>(q2);
        const uint4 lA4 = *reinterpret_cast<const uint4*>(q1 + 64);
        const uint4 lB4 = *reinterpret_cast<const uint4*>(q2 + 64);
        qh[0][0] = hA.x; qh[0][1] = hB.x; qh[0][2] = hA.y; qh[0][3] = hB.y;
        qh[1][0] = hA.z; qh[1][1] = hB.z; qh[1][2] = hA.w; qh[1][3] = hB.w;
        ql[0][0] = lA4.x; ql[0][1] = lB4.x; ql[0][2] = lA4.y; ql[0][3] = lB4.y;
        ql[1][0] = lA4.z; ql[1][1] = lB4.z; ql[1][2] = lA4.w; ql[1][3] = lB4.w;
    }

    float o[5][4];
#pragma unroll
    for (int i = 0; i < 5; i++)
#pragma unroll
        for (int k = 0; k < 4; k++) o[i][k] = 0.f;
    float mA = -1e30f, mB = -1e30f;   // invariant: integer after first tile
    const float fzero = 0.f;
    const uint32_t ones = (g == 0) ? 0x3C003C00u : 0u;
    uint32_t P[16];                    // packed P of the previous tile

    const int kwoff = (64 * ch + g) * KROW + 16 * tig;
    const int vwoff = g * VROW + ch * 128 + 16 * tig;

    // ---- S + epilogue: computes c = S(t), then P/m/o-rescale ----
    auto s_phase = [&](const char* Kb, float c[8][4]) {
#pragma unroll
        for (int nt = 0; nt < 8; nt++) {
            const char* kr = Kb + nt * 8 * KROW;
            const uint4 bh = *reinterpret_cast<const uint4*>(kr);
            const uint4 bl = *reinterpret_cast<const uint4*>(kr + 64);
            MMA4Z(c[nt], qh[0][0], qh[0][1], qh[0][2], qh[0][3], bh.x, bh.y, fzero);
            MMA4(c[nt], qh[0][0], qh[0][1], qh[0][2], qh[0][3], bl.x, bl.y);
            MMA4(c[nt], ql[0][0], ql[0][1], ql[0][2], ql[0][3], bh.x, bh.y);
            MMA4(c[nt], qh[1][0], qh[1][1], qh[1][2], qh[1][3], bh.z, bh.w);
            MMA4(c[nt], qh[1][0], qh[1][1], qh[1][2], qh[1][3], bl.z, bl.w);
            MMA4(c[nt], ql[1][0], ql[1][1], ql[1][2], ql[1][3], bh.z, bh.w);
        }
    };
    auto epi_phase = [&](float c[8][4]) {
        float mxA = fmaxf(c[0][0], c[0][1]);
        float mxB = fmaxf(c[0][2], c[0][3]);
#pragma unroll
        for (int nt = 1; nt < 8; nt++) {
            mxA = fmaxf(mxA, fmaxf(c[nt][0], c[nt][1]));
            mxB = fmaxf(mxB, fmaxf(c[nt][2], c[nt][3]));
        }
        mxA = fmaxf(mxA, __shfl_xor_sync(0xffffffffu, mxA, 1));
        mxA = fmaxf(mxA, __shfl_xor_sync(0xffffffffu, mxA, 2));
        mxB = fmaxf(mxB, __shfl_xor_sync(0xffffffffu, mxB, 1));
        mxB = fmaxf(mxB, __shfl_xor_sync(0xffffffffu, mxB, 2));
        const float mxAq = (mxA + 12582912.0f) - 12582912.0f;   // integer quantize
        const float mxBq = (mxB + 12582912.0f) - 12582912.0f;
        const float mAn = fmaxf(mA, mxAq);
        const float mBn = fmaxf(mB, mxBq);
        const float sA  = fexp2(fmaxf(mA - mAn, -126.f));
        const float sB  = fexp2(fmaxf(mB - mBn, -126.f));
        mA = mAn; mB = mBn;
#pragma unroll
        for (int nt = 0; nt < 5; nt++) {
            o[nt][0] *= sA; o[nt][1] *= sA;
            o[nt][2] *= sB; o[nt][3] *= sB;
        }
        const float K1A = 12582912.0f - mA;
        const float K1B = 12582912.0f - mB;
#pragma unroll
        for (int nt = 0; nt < 8; nt++) {
            c[nt][0] = fexp2f(c[nt][0], K1A);
            c[nt][1] = fexp2f(c[nt][1], K1A);
            c[nt][2] = fexp2f(c[nt][2], K1B);
            c[nt][3] = fexp2f(c[nt][3], K1B);
        }
#pragma unroll
        for (int p = 0; p < 2; p++) {
            P[p*8+0] = pkh2(c[4*p][0],   c[4*p][1]);
            P[p*8+1] = pkh2(c[4*p][2],   c[4*p][3]);
            P[p*8+2] = pkh2(c[4*p+1][0], c[4*p+1][1]);
            P[p*8+3] = pkh2(c[4*p+1][2], c[4*p+1][3]);
            P[p*8+4] = pkh2(c[4*p+2][0], c[4*p+2][1]);
            P[p*8+5] = pkh2(c[4*p+2][2], c[4*p+2][3]);
            P[p*8+6] = pkh2(c[4*p+3][0], c[4*p+3][1]);
            P[p*8+7] = pkh2(c[4*p+3][2], c[4*p+3][3]);
        }
    };
    auto o_phase = [&](const char* Vh) {
#pragma unroll
        for (int p = 0; p < 2; p++) {
#pragma unroll
            for (int nt = 0; nt < 4; nt++) {
                const uint4 vh4 = *reinterpret_cast<const uint4*>(Vh + nt * 8 * VROW + p * 64);
                MMA4(o[nt], P[p*8+0], P[p*8+1], P[p*8+2], P[p*8+3], vh4.x, vh4.y);
                MMA4(o[nt], P[p*8+4], P[p*8+5], P[p*8+6], P[p*8+7], vh4.z, vh4.w);
            }
            MMA4(o[4], P[p*8+0], P[p*8+1], P[p*8+2], P[p*8+3], ones, ones);
            MMA4(o[4], P[p*8+4], P[p*8+5], P[p*8+6], P[p*8+7], ones, ones);
        }
    };

    // ---- prologue: tile 0 ----
    asm volatile("cp.async.wait_group 1;" ::: "memory");
    __syncthreads();
    {
        float c[8][4];
        s_phase(smem + SM_K + kwoff, c);
        epi_phase(c);
    }

    // ---- pipelined mainloop: iter u handles S(u+1) + O(u) + epi(u+1) ----
    for (int u = 0; u < NT - 1; u++) {
        asm volatile("cp.async.wait_group 0;" ::: "memory");
        __syncthreads();   // tile u+1 ready; V(u-1)/K(u) readers done

        if (u + 2 < NT) {
            issue_tile(u + 2);
            asm volatile("cp.async.commit_group;" ::: "memory");
        }

        float c[8][4];
        s_phase(smem + SM_K + ((u + 1) & 1) * KBUF + kwoff, c);   // S(u+1)
        o_phase(smem + SM_V + (u % 3) * VBUF + vwoff);            // O(u), indep stream
        epi_phase(c);                                             // P(u+1), rescale o
    }
    o_phase(smem + SM_V + ((NT - 1) % 3) * VBUF + vwoff);         // O(NT-1)

    // ---- extract l (col 0 of ones-channel lives in tig==0 lanes) ----
    const int qroot = lane & ~3;
    const float lA = __shfl_sync(0xffffffffu, o[4][0], qroot);
    const float lB = __shfl_sync(0xffffffffu, o[4][2], qroot);

    // ---- combine column halves (max-aware) ----
    float* ost = reinterpret_cast<float*>(smem + SM_V);         // vbuf0 (V(35) in vbuf2)
    float* ls  = reinterpret_cast<float*>(smem + SM_LS);
    float* ms  = reinterpret_cast<float*>(smem + SM_MS);
    float* ys  = reinterpret_cast<float*>(smem + SM_K);         // kbuf0 (K(35) in kbuf1)
    float* wo  = reinterpret_cast<float*>(smem + SM_K + 16384);

    const int rA = 16 * wq + g, rB = rA + 8;
    if (ch == 1) {
#pragma unroll
        for (int nt = 0; nt < 4; nt++) {
            const int ci = 8 * nt + 2 * tig;
            ost[rA * 34 + ci]     = o[nt][0];
            ost[rA * 34 + ci + 1] = o[nt][1];
            ost[rB * 34 + ci]     = o[nt][2];
            ost[rB * 34 + ci + 1] = o[nt][3];
        }
        if (tig == 0) { ls[rA] = lA; ls[rB] = lB; ms[rA] = mA; ms[rB] = mB; }
    }
    for (int i = tid; i < C_ * CI; i += 256) wo[i] = w_out[i];
    __syncthreads();

    if (ch == 0) {
        const float m1A = ms[rA], m1B = ms[rB];
        const float MtA = fmaxf(mA, m1A), MtB = fmaxf(mB, m1B);
        const float a0 = fexp2(fmaxf(mA - MtA, -126.f));
        const float a1 = fexp2(fmaxf(m1A - MtA, -126.f));
        const float b0 = fexp2(fmaxf(mB - MtB, -126.f));
        const float b1 = fexp2(fmaxf(m1B - MtB, -126.f));
        const float iA = 1.f / (lA * a0 + ls[rA] * a1);
        const float iB = 1.f / (lB * b0 + ls[rB] * b1);
        const float fA0 = a0 * iA, fA1 = a1 * iA;
        const float fB0 = b0 * iB, fB1 = b1 * iB;
#pragma unroll
        for (int nt = 0; nt < 4; nt++) {
            const int ci = 8 * nt + 2 * tig;
            ys[rA * 33 + ci]     = o[nt][0] * fA0 + ost[rA * 34 + ci]     * fA1;
            ys[rA * 33 + ci + 1] = o[nt][1] * fA0 + ost[rA * 34 + ci + 1] * fA1;
            ys[rB * 33 + ci]     = o[nt][2] * fB0 + ost[rB * 34 + ci]     * fB1;
            ys[rB * 33 + ci + 1] = o[nt][3] * fB0 + ost[rB * 34 + ci + 1] * fB1;
        }
    }
    __syncthreads();

    // ---- out-proj + residual ----
    {
        const int r  = tid & 63;
        const int cq = tid >> 6;
        float y[CI];
#pragma unroll
        for (int i = 0; i < CI; i++) y[i] = ys[r * 33 + i];
        const float* xb = x   + (size_t)b * C_ * N_;
        float*       ob = out + (size_t)b * C_ * N_;
#pragma unroll 4
        for (int c = cq * 16; c < cq * 16 + 16; c++) {
            float acc = __ldg(&b_out[c]);
            const float* w = &wo[c * CI];
#pragma unroll
            for (int i = 0; i < CI; i++) acc += y[i] * w[i];
            const size_t gi = (size_t)c * N_ + n0 + r;
            ob[gi] = acc + xb[gi];
        }
    }
}

// =====================================================================
extern "C" void kernel_launch(void* const* d_in, const int* in_sizes, int n_in,
                              void* d_out, int out_size)
{
    const float* x  = (const float*)d_in[0];
    const float* wt = (const float*)d_in[1];
    const float* bt = (const float*)d_in[2];
    const float* wp = (const float*)d_in[3];
    const float* bp = (const float*)d_in[4];
    const float* wg = (const float*)d_in[5];
    const float* bg = (const float*)d_in[6];
    const float* wo = (const float*)d_in[7];
    const float* bo = (const float*)d_in[8];
    float* out = (float*)d_out;

    static bool attr_set = false;
    if (!attr_set) {
        cudaFuncSetAttribute(attn_kernel, cudaFuncAttributeMaxDynamicSharedMemorySize, SMEM_TOTAL);
        attr_set = true;
    }

    proj_kernel<<<dim3(N_ / 64, B_), 256>>>(x, wt, bt, wp, bp, wg, bg);
    attn_kernel<<<dim3(N_ / 64, B_), 256, SMEM_TOTAL>>>(x, wo, bo, out);
}

// round 11
// speedup vs baseline: 1.2339x; 1.2339x over previous
#include <cuda_runtime.h>
#include <cuda_fp16.h>
#include <cstdint>

// ---------------- problem constants ----------------
constexpr int B_  = 4;
constexpr int C_  = 64;
constexpr int HH  = 96;
constexpr int WW  = 96;
constexpr int N_  = HH * WW;        // 9216
constexpr int M_  = N_ / 2;         // 4608
constexpr int CI  = 32;
constexpr int TKV = 128;            // kv tile
constexpr int NT  = M_ / TKV;       // 36

// ---------------- scratch ----------------
// theta rows: [b][n][64] fp16: halfwords 0-31 = hi (word-permuted), 32-63 = lo
// theta pre-scaled by log2(e): softmax in exp2 domain.
__device__ __half g_theta[(size_t)B_ * N_ * 64];
// phi rows: [b][m][32] fp16 SINGLE precision (word-permuted)
__device__ __half g_phi[(size_t)B_ * M_ * 32];
// V: [b][ci][m] fp16, m permuted within 64-element runs
__device__ __half g_v[(size_t)B_ * CI * M_];

// ---------------- smem map (bytes, dynamic) ----------------
constexpr int KBUF = 8192;         // 128 x 64B (single-fp16 K, zero padding)
constexpr int VBUF = 10240;        // 32 x 320B
constexpr int SM_Q   = 0;          // 12288
constexpr int SM_K   = 12288;      // 2 x KBUF = 16384
constexpr int SM_V   = 28672;      // 2 x VBUF = 20480
constexpr int SM_LS  = 49152;      // 64 f32
constexpr int SM_MS  = 49408;      // 64 f32
constexpr int SMEM_TOTAL = 49664;  // x2 CTAs = 99KB
constexpr int QROW = 192;   // Q row stride (12 == 4 mod 8 -> conflict-free)
constexpr int KROW = 64;    // K row stride  (4 == 4 mod 8 -> conflict-free, no pad)
constexpr int VROW = 320;   // V row stride (20 == 4 mod 8)

// word permutation: within a 16-word group, logical word w -> phys 4*(w%4)+(w/4)
__host__ __device__ __forceinline__ int permw16(int w) {
    return (w & ~15) | ((w & 3) << 2) | ((w & 15) >> 2);
}

// ---------------- helpers ----------------
__device__ __forceinline__ uint32_t smem_u32(const void* p) {
    uint32_t a;
    asm("{ .reg .u64 t; cvta.to.shared.u64 t, %1; cvt.u32.u64 %0, t; }" : "=r"(a) : "l"(p));
    return a;
}

#define MMA4(cv, a0, a1, a2, a3, b0v, b1v)                                        \
    asm volatile("mma.sync.aligned.m16n8k16.row.col.f32.f16.f16.f32 "             \
        "{%0,%1,%2,%3}, {%4,%5,%6,%7}, {%8,%9}, {%0,%1,%2,%3};"                   \
        : "+f"((cv)[0]), "+f"((cv)[1]), "+f"((cv)[2]), "+f"((cv)[3])              \
        : "r"(a0), "r"(a1), "r"(a2), "r"(a3), "r"(b0v), "r"(b1v))

// D = A*B + 0 (separate zero C operand: avoids accumulator MOV-inits)
#define MMA4Z(cv, a0, a1, a2, a3, b0v, b1v, zz)                                   \
    asm volatile("mma.sync.aligned.m16n8k16.row.col.f32.f16.f16.f32 "             \
        "{%0,%1,%2,%3}, {%4,%5,%6,%7}, {%8,%9}, {%10,%10,%10,%10};"               \
        : "=f"((cv)[0]), "=f"((cv)[1]), "=f"((cv)[2]), "=f"((cv)[3])              \
        : "r"(a0), "r"(a1), "r"(a2), "r"(a3), "r"(b0v), "r"(b1v), "f"(zz))

#define CP16(dst, src)                                                            \
    asm volatile("cp.async.cg.shared.global [%0], [%1], 16;" :: "r"(dst), "l"(src) : "memory")

// exp2, deg-4 Taylor, FMA pipe only. Rescale args are exact integer diffs.
__device__ __forceinline__ float fexp2(float d) {
    float t = d + 12582912.0f;
    float f = d - (t - 12582912.0f);
    float p = 0.00961813f;
    p = fmaf(p, f, 0.05550411f);
    p = fmaf(p, f, 0.24022651f);
    p = fmaf(p, f, 0.69314718f);
    p = fmaf(p, f, 1.0f);
    return __int_as_float(__float_as_int(t) * 8388608 + __float_as_int(p));
}

// exp2(c - m) with INTEGER m folded into K1 = 12582912 - m (exact).
__device__ __forceinline__ float fexp2f(float c, float K1) {
    float t = c + K1;
    float u = K1 - t;
    float f = u + c;
    float p = 0.00961813f;
    p = fmaf(p, f, 0.05550411f);
    p = fmaf(p, f, 0.24022651f);
    p = fmaf(p, f, 0.69314718f);
    p = fmaf(p, f, 1.0f);
    return __int_as_float(__float_as_int(t) * 8388608 + __float_as_int(p));
}

__device__ __forceinline__ uint32_t pkh2(float a, float b) {
    __half2 h = __floats2half2_rn(a, b);
    uint32_t u; *reinterpret_cast<__half2*>(&u) = h;
    return u;
}

// =====================================================================
// Kernel A: projections -> fp16 scratch (theta hi/lo, phi single, V single)
// grid (144, 4), 256 threads
// =====================================================================
__global__ __launch_bounds__(256)
void proj_kernel(const float* __restrict__ x,
                 const float* __restrict__ wt, const float* __restrict__ bt,
                 const float* __restrict__ wp, const float* __restrict__ bp,
                 const float* __restrict__ wg, const float* __restrict__ bg)
{
    __shared__ float xs[C_][64];
    __shared__ float ws[3][CI][C_];
    __shared__ float bs[3][CI];

    const int b   = blockIdx.y;
    const int n0  = blockIdx.x * 64;
    const int m0  = blockIdx.x * 32;
    const int tid = threadIdx.x;

    float* wflat = &ws[0][0][0];
    for (int i = tid; i < CI * C_; i += 256) {
        wflat[i]               = wt[i];
        wflat[CI * C_ + i]     = wp[i];
        wflat[2 * CI * C_ + i] = wg[i];
    }
    if (tid < CI) { bs[0][tid] = bt[tid]; bs[1][tid] = bp[tid]; bs[2][tid] = bg[tid]; }
    for (int idx = tid; idx < C_ * 64; idx += 256) {
        const int c = idx >> 6, j = idx & 63;
        xs[c][j] = x[((size_t)b * C_ + c) * N_ + n0 + j];
    }
    __syncthreads();

    const int j   = tid & 63;
    const int cib = tid >> 6;
    float tacc[8];
#pragma unroll
    for (int u = 0; u < 8; u++) tacc[u] = bs[0][cib + 4 * u];
#pragma unroll 4
    for (int c = 0; c < C_; c++) {
        const float xv = xs[c][j];
#pragma unroll
        for (int u = 0; u < 8; u++) tacc[u] += xv * ws[0][cib + 4 * u][c];
    }

    const int jp  = tid & 31;
    const int cjb = tid >> 5;
    float pv[4], gv[4];
    {
        float p0[4], p1[4], q0[4], q1[4];
#pragma unroll
        for (int u = 0; u < 4; u++) { p0[u] = p1[u] = q0[u] = q1[u] = 0.f; }
#pragma unroll 4
        for (int c = 0; c < C_; c++) {
            const float x0 = xs[c][2 * jp];
            const float x1 = xs[c][2 * jp + 1];
#pragma unroll
            for (int u = 0; u < 4; u++) {
                const float wpv = ws[1][cjb + 8 * u][c];
                const float wgv = ws[2][cjb + 8 * u][c];
                p0[u] += x0 * wpv;  p1[u] += x1 * wpv;
                q0[u] += x0 * wgv;  q1[u] += x1 * wgv;
            }
        }
#pragma unroll
        for (int u = 0; u < 4; u++) {
            const int ci = cjb + 8 * u;
            pv[u] = bs[1][ci] + fmaxf(p0[u], p1[u]);
            gv[u] = bs[2][ci] + fmaxf(q0[u], q1[u]);
        }
    }
    __syncthreads();

    __half* sth = reinterpret_cast<__half*>(wflat);              // 64 x 64 halves
    __half* sph = reinterpret_cast<__half*>(wflat + CI * C_);    // 32 x 32 halves
#pragma unroll
    for (int u = 0; u < 8; u++) {
        const int ci  = cib + 4 * u;
        const int pos = permw16(ci >> 1) * 2 + (ci & 1);
        const float v = tacc[u] * 1.4426950408889634f;
        const __half h = __float2half_rn(v);
        sth[j * 64 + pos]      = h;
        sth[j * 64 + 32 + pos] = __float2half_rn(v - __half2float(h));
    }
#pragma unroll
    for (int u = 0; u < 4; u++) {
        const int ci  = cjb + 8 * u;
        const int pos = permw16(ci >> 1) * 2 + (ci & 1);
        sph[jp * 32 + pos] = __float2half_rn(pv[u]);   // single precision phi
        {
            const int m    = m0 + jp;
            const int mloc = m & 63;
            const int mp   = (m & ~63) | (permw16(mloc >> 1) * 2 + (mloc & 1));
            g_v[((size_t)b * CI + ci) * M_ + mp] = __float2half_rn(gv[u]);
        }
    }
    __syncthreads();

    for (int idx = tid; idx < 512; idx += 256) {       // theta: 64 rows x 8 chunks
        const int r = idx >> 3, c = idx & 7;
        *reinterpret_cast<uint4*>(&g_theta[((size_t)b * N_ + n0 + r) * 64 + c * 8]) =
            *reinterpret_cast<const uint4*>(&sth[r * 64 + c * 8]);
    }
    for (int idx = tid; idx < 128; idx += 256) {       // phi: 32 rows x 4 chunks
        const int r = idx >> 2, c = idx & 3;
        *reinterpret_cast<uint4*>(&g_phi[((size_t)b * M_ + m0 + r) * 32 + c * 8]) =
            *reinterpret_cast<const uint4*>(&sph[r * 32 + c * 8]);
    }
}

// =====================================================================
// Kernel B: mma.sync fp16 flash attention (integer online max, MMA-computed l,
//           single-fp16 K -> 2-product S)
// grid (144, 4), 256 threads (8 warps), 2 CTAs/SM
// =====================================================================
__global__ __launch_bounds__(256, 2)
void attn_kernel(const float* __restrict__ x,
                 const float* __restrict__ w_out,
                 const float* __restrict__ b_out,
                 float* __restrict__ out)
{
    extern __shared__ char smem[];
    const uint32_t sbase = smem_u32(smem);
    const int tid  = threadIdx.x;
    const int wid  = tid >> 5;
    const int lane = tid & 31;
    const int wq   = wid & 3;
    const int ch   = wid >> 2;
    const int g    = lane >> 2;
    const int tig  = lane & 3;
    const int b    = blockIdx.y;
    const int n0   = blockIdx.x * 64;

    const __half* Qg = g_theta + ((size_t)b * N_ + n0) * 64;
    const __half* Kg = g_phi   + (size_t)b * M_ * 32;
    const __half* Vg = g_v     + (size_t)b * CI * M_;

    // ---- stage Q ----
    for (int i = tid; i < 512; i += 256) {
        const int r = i >> 3, c = i & 7;
        *reinterpret_cast<uint4*>(smem + SM_Q + r * QROW + c * 16) =
            *reinterpret_cast<const uint4*>(Qg + (size_t)r * 64 + c * 8);
    }

    const int kc = tid & 3;       // K: 128 rows x 4 chunks = 512, 2/thread
    const int vc = tid & 15;      // V: 32 rows x 16 chunks = 512, 2/thread
    auto issue_tile = [&](int t, int buf) {
        const __half* kb = Kg + (size_t)t * TKV * 32;
        const __half* vb = Vg + (size_t)t * TKV;
        const uint32_t kd = sbase + SM_K + buf * KBUF;
        const uint32_t vd = sbase + SM_V + buf * VBUF;
#pragma unroll
        for (int i = 0; i < 2; i++) {
            const int r = (tid + i * 256) >> 2;
            CP16(kd + r * KROW + kc * 16, kb + (size_t)r * 32 + kc * 8);
        }
#pragma unroll
        for (int i = 0; i < 2; i++) {
            const int ci = (tid + i * 256) >> 4;
            CP16(vd + ci * VROW + vc * 16, vb + (size_t)ci * M_ + vc * 8);
        }
    };

    issue_tile(0, 0);
    asm volatile("cp.async.commit_group;" ::: "memory");
    __syncthreads();   // Q stores visible

    // ---- Q fragments (permuted layout -> LDS.128 quads) ----
    uint32_t qh[2][4], ql[2][4];
    {
        const char* q1 = smem + SM_Q + (16 * wq + g) * QROW + 16 * tig;
        const char* q2 = smem + SM_Q + (16 * wq + g + 8) * QROW + 16 * tig;
        const uint4 hA = *reinterpret_cast<const uint4*>(q1);
        const uint4 hB = *reinterpret_cast<const uint4*>(q2);
        const uint4 lA4 = *reinterpret_cast<const uint4*>(q1 + 64);
        const uint4 lB4 = *reinterpret_cast<const uint4*>(q2 + 64);
        qh[0][0] = hA.x; qh[0][1] = hB.x; qh[0][2] = hA.y; qh[0][3] = hB.y;
        qh[1][0] = hA.z; qh[1][1] = hB.z; qh[1][2] = hA.w; qh[1][3] = hB.w;
        ql[0][0] = lA4.x; ql[0][1] = lB4.x; ql[0][2] = lA4.y; ql[0][3] = lB4.y;
        ql[1][0] = lA4.z; ql[1][1] = lB4.z; ql[1][2] = lA4.w; ql[1][3] = lB4.w;
    }

    // o[0..3]: ci 0..31; o[4]: virtual ones-channel (col 0 = row-sum l)
    float o[5][4];
#pragma unroll
    for (int i = 0; i < 5; i++)
#pragma unroll
        for (int k = 0; k < 4; k++) o[i][k] = 0.f;
    float mA = -1e30f, mB = -1e30f;   // invariant: integer after first tile
    const float fzero = 0.f;
    const uint32_t ones = (g == 0) ? 0x3C003C00u : 0u;

    const int kwoff = (64 * ch + g) * KROW + 16 * tig;
    const int vwoff = g * VROW + ch * 128 + 16 * tig;

    for (int u = 0; u < NT; u++) {
        asm volatile("cp.async.wait_group 0;" ::: "memory");
        __syncthreads();   // tile u ready; all warps done with buffer (u+1)&1

        if (u + 1 < NT) {
            issue_tile(u + 1, (u + 1) & 1);
            asm volatile("cp.async.commit_group;" ::: "memory");
        }

        const int buf = u & 1;
        const char* Kb = smem + SM_K + buf * KBUF + kwoff;
        const char* Vh = smem + SM_V + buf * VBUF + vwoff;

        // ---- S = Q K^T : 8 n-tiles x (1 LDS.128 + 4 HMMA) ----
        float c[8][4];
#pragma unroll
        for (int nt = 0; nt < 8; nt++) {
            const uint4 bh = *reinterpret_cast<const uint4*>(Kb + nt * 8 * KROW);
            MMA4Z(c[nt], qh[0][0], qh[0][1], qh[0][2], qh[0][3], bh.x, bh.y, fzero);
            MMA4(c[nt], ql[0][0], ql[0][1], ql[0][2], ql[0][3], bh.x, bh.y);
            MMA4(c[nt], qh[1][0], qh[1][1], qh[1][2], qh[1][3], bh.z, bh.w);
            MMA4(c[nt], ql[1][0], ql[1][1], ql[1][2], ql[1][3], bh.z, bh.w);
        }

        // ---- running max (quantized to INTEGER) + O rescale ----
        float mxA = fmaxf(c[0][0], c[0][1]);
        float mxB = fmaxf(c[0][2], c[0][3]);
#pragma unroll
        for (int nt = 1; nt < 8; nt++) {
            mxA = fmaxf(mxA, fmaxf(c[nt][0], c[nt][1]));
            mxB = fmaxf(mxB, fmaxf(c[nt][2], c[nt][3]));
        }
        mxA = fmaxf(mxA, __shfl_xor_sync(0xffffffffu, mxA, 1));
        mxA = fmaxf(mxA, __shfl_xor_sync(0xffffffffu, mxA, 2));
        mxB = fmaxf(mxB, __shfl_xor_sync(0xffffffffu, mxB, 1));
        mxB = fmaxf(mxB, __shfl_xor_sync(0xffffffffu, mxB, 2));
        const float mxAq = (mxA + 12582912.0f) - 12582912.0f;   // integer quantize
        const float mxBq = (mxB + 12582912.0f) - 12582912.0f;
        const float mAn = fmaxf(mA, mxAq);
        const float mBn = fmaxf(mB, mxBq);
        const float sA  = fexp2(fmaxf(mA - mAn, -126.f));       // integer args -> exact
        const float sB  = fexp2(fmaxf(mB - mBn, -126.f));
        mA = mAn; mB = mBn;
#pragma unroll
        for (int nt = 0; nt < 5; nt++) {
            o[nt][0] *= sA; o[nt][1] *= sA;
            o[nt][2] *= sB; o[nt][3] *= sB;
        }

        // ---- exp2(s - m): integer max folded into range-reduction constant ----
        const float K1A = 12582912.0f - mA;
        const float K1B = 12582912.0f - mB;
#pragma unroll
        for (int nt = 0; nt < 8; nt++) {
            c[nt][0] = fexp2f(c[nt][0], K1A);
            c[nt][1] = fexp2f(c[nt][1], K1A);
            c[nt][2] = fexp2f(c[nt][2], K1B);
            c[nt][3] = fexp2f(c[nt][3], K1B);
        }

        // ---- O += P V (fp16 single product); l-column via constant fragment ----
#pragma unroll
        for (int p = 0; p < 2; p++) {
            uint32_t pa0[4], pa1[4];
            pa0[0] = pkh2(c[4*p][0],   c[4*p][1]);
            pa0[1] = pkh2(c[4*p][2],   c[4*p][3]);
            pa0[2] = pkh2(c[4*p+1][0], c[4*p+1][1]);
            pa0[3] = pkh2(c[4*p+1][2], c[4*p+1][3]);
            pa1[0] = pkh2(c[4*p+2][0], c[4*p+2][1]);
            pa1[1] = pkh2(c[4*p+2][2], c[4*p+2][3]);
            pa1[2] = pkh2(c[4*p+3][0], c[4*p+3][1]);
            pa1[3] = pkh2(c[4*p+3][2], c[4*p+3][3]);
#pragma unroll
            for (int nt = 0; nt < 4; nt++) {
                const uint4 vh4 = *reinterpret_cast<const uint4*>(Vh + nt * 8 * VROW + p * 64);
                MMA4(o[nt], pa0[0], pa0[1], pa0[2], pa0[3], vh4.x, vh4.y);
                MMA4(o[nt], pa1[0], pa1[1], pa1[2], pa1[3], vh4.z, vh4.w);
            }
            MMA4(o[4], pa0[0], pa0[1], pa0[2], pa0[3], ones, ones);
            MMA4(o[4], pa1[0], pa1[1], pa1[2], pa1[3], ones, ones);
        }
    }

    // ---- extract l (col 0 of ones-channel lives in tig==0 lanes) ----
    const int qroot = lane & ~3;
    const float lA = __shfl_sync(0xffffffffu, o[4][0], qroot);
    const float lB = __shfl_sync(0xffffffffu, o[4][2], qroot);

    __syncthreads();   // ALL warps done reading K/V bufs before smem reuse (fixes R9 latent race)

    // ---- combine column halves (max-aware) ----
    float* ost = reinterpret_cast<float*>(smem + SM_V);         // [64][34] in vbuf0
    float* ls  = reinterpret_cast<float*>(smem + SM_LS);
    float* ms  = reinterpret_cast<float*>(smem + SM_MS);
    float* ys  = reinterpret_cast<float*>(smem + SM_K);         // [64][33] in K bufs
    float* wo  = reinterpret_cast<float*>(smem + SM_V + VBUF);  // [64][32] in vbuf1

    const int rA = 16 * wq + g, rB = rA + 8;
    if (ch == 1) {
#pragma unroll
        for (int nt = 0; nt < 4; nt++) {
            const int ci = 8 * nt + 2 * tig;
            ost[rA * 34 + ci]     = o[nt][0];
            ost[rA * 34 + ci + 1] = o[nt][1];
            ost[rB * 34 + ci]     = o[nt][2];
            ost[rB * 34 + ci + 1] = o[nt][3];
        }
        if (tig == 0) { ls[rA] = lA; ls[rB] = lB; ms[rA] = mA; ms[rB] = mB; }
    }
    for (int i = tid; i < C_ * CI; i += 256) wo[i] = w_out[i];
    __syncthreads();

    if (ch == 0) {
        const float m1A = ms[rA], m1B = ms[rB];
        const float MtA = fmaxf(mA, m1A), MtB = fmaxf(mB, m1B);
        const float a0 = fexp2(fmaxf(mA - MtA, -126.f));
        const float a1 = fexp2(fmaxf(m1A - MtA, -126.f));
        const float b0 = fexp2(fmaxf(mB - MtB, -126.f));
        const float b1 = fexp2(fmaxf(m1B - MtB, -126.f));
        const float iA = 1.f / (lA * a0 + ls[rA] * a1);
        const float iB = 1.f / (lB * b0 + ls[rB] * b1);
        const float fA0 = a0 * iA, fA1 = a1 * iA;
        const float fB0 = b0 * iB, fB1 = b1 * iB;
#pragma unroll
        for (int nt = 0; nt < 4; nt++) {
            const int ci = 8 * nt + 2 * tig;
            ys[rA * 33 + ci]     = o[nt][0] * fA0 + ost[rA * 34 + ci]     * fA1;
            ys[rA * 33 + ci + 1] = o[nt][1] * fA0 + ost[rA * 34 + ci + 1] * fA1;
            ys[rB * 33 + ci]     = o[nt][2] * fB0 + ost[rB * 34 + ci]     * fB1;
            ys[rB * 33 + ci + 1] = o[nt][3] * fB0 + ost[rB * 34 + ci + 1] * fB1;
        }
    }
    __syncthreads();

    // ---- out-proj + residual: thread = (row r, 16 channels) ----
    {
        const int r  = tid & 63;
        const int cq = tid >> 6;
        float y[CI];
#pragma unroll
        for (int i = 0; i < CI; i++) y[i] = ys[r * 33 + i];
        const float* xb = x   + (size_t)b * C_ * N_;
        float*       ob = out + (size_t)b * C_ * N_;
#pragma unroll 4
        for (int c = cq * 16; c < cq * 16 + 16; c++) {
            float acc = __ldg(&b_out[c]);
            const float* w = &wo[c * CI];
#pragma unroll
            for (int i = 0; i < CI; i++) acc += y[i] * w[i];
            const size_t gi = (size_t)c * N_ + n0 + r;
            ob[gi] = acc + xb[gi];
        }
    }
}

// =====================================================================
extern "C" void kernel_launch(void* const* d_in, const int* in_sizes, int n_in,
                              void* d_out, int out_size)
{
    const float* x  = (const float*)d_in[0];
    const float* wt = (const float*)d_in[1];
    const float* bt = (const float*)d_in[2];
    const float* wp = (const float*)d_in[3];
    const float* bp = (const float*)d_in[4];
    const float* wg = (const float*)d_in[5];
    const float* bg = (const float*)d_in[6];
    const float* wo = (const float*)d_in[7];
    const float* bo = (const float*)d_in[8];
    float* out = (float*)d_out;

    static bool attr_set = false;
    if (!attr_set) {
        cudaFuncSetAttribute(attn_kernel, cudaFuncAttributeMaxDynamicSharedMemorySize, SMEM_TOTAL);
        attr_set = true;
    }

    proj_kernel<<<dim3(N_ / 64, B_), 256>>>(x, wt, bt, wp, bp, wg, bg);
    attn_kernel<<<dim3(N_ / 64, B_), 256, SMEM_TOTAL>>>(x, wo, bo, out);
}